// round 14
// baseline (speedup 1.0000x reference)
#include <cuda_runtime.h>
#include <cstdint>

typedef unsigned long long u64;

// ---------- device scratch ----------
__device__ float g_feat[4 * 64 * 64 * 64];      // NHWC feat[pix][64]
__device__ float g_wk[4 * 64 * 64 * 100];       // softmaxed kernels
__device__ u64   g_wc2[2 * 256 * 16];           // k1 weights: [hf][c][16] pairs (m,m+1)
__device__ u64   g_wp2[64 * 9 * 4 * 14];        // k2 weights: [i][t][p][14] pairs (k,k+1), padded

// ---------- f32x2 helpers ----------
__device__ __forceinline__ u64 pack2(float lo, float hi) {
    u64 r; asm("mov.b64 %0, {%1, %2};" : "=l"(r) : "f"(lo), "f"(hi)); return r;
}
__device__ __forceinline__ void unpack2(u64 v, float& lo, float& hi) {
    asm("mov.b64 {%0, %1}, %2;" : "=f"(lo), "=f"(hi) : "l"(v));
}
__device__ __forceinline__ u64 fma2(u64 a, u64 b, u64 c) {
    u64 d; asm("fma.rn.f32x2 %0, %1, %2, %3;" : "=l"(d) : "l"(a), "l"(b), "l"(c)); return d;
}

// ============================================================
// K0a: pack k1 weights (wc2)
// ============================================================
__global__ void k0a_pack(const float* __restrict__ Wc) {
    int e = blockIdx.x * 256 + threadIdx.x;
    if (e < 8192) {
        int j = e & 15, c = (e >> 4) & 255, hf = e >> 12;
        int m0 = hf * 32 + 2 * j;
        g_wc2[e] = pack2(Wc[(size_t)m0 * 256 + c], Wc[(size_t)(m0 + 1) * 256 + c]);
    }
}

// ============================================================
// K0b: pack k2 weights (wp2) — runs between k1 and k2
// ============================================================
__global__ void k0b_pack(const float* __restrict__ We) {
    int e2 = blockIdx.x * 256 + threadIdx.x;
    if (e2 < 32256) {
        int kp = e2 % 14;
        int p  = (e2 / 14) & 3;
        int t  = (e2 / 56) % 9;
        int i  = e2 / 504;
        int o0 = p * 25 + 2 * kp;
        float lo = (2 * kp < 25)     ? We[(size_t)o0 * 576 + i * 9 + t] : 0.f;
        float hi = (2 * kp + 1 < 25) ? We[(size_t)(o0 + 1) * 576 + i * 9 + t] : 0.f;
        g_wp2[e2] = pack2(lo, hi);
    }
}

// ============================================================
// K1: feat = relu(Wc @ x + bc), NHWC output (R2 EXACT)
// ============================================================
#define K1_SMEM (4096 * 8)

__global__ __launch_bounds__(128) void k1_compress(const float* __restrict__ x,
                                                   const float* __restrict__ bc) {
    extern __shared__ u64 ws[];
    int tid = threadIdx.x;
    int hf  = blockIdx.x & 1;
    int pix = (blockIdx.x >> 1) * 128 + tid;

    const u64* src = g_wc2 + hf * 4096;
    for (int e = tid; e < 4096; e += 128) ws[e] = src[e];
    __syncthreads();

    int bb = pix >> 12, hw = pix & 4095;
    const float* xp = x + ((size_t)bb << 20) + hw;

    u64 acc[16];
#pragma unroll
    for (int j = 0; j < 16; j++) acc[j] = 0ull;

    for (int c = 0; c < 256; c += 4) {
        float xv[4];
#pragma unroll
        for (int u = 0; u < 4; u++) xv[u] = __ldg(xp + (size_t)(c + u) * 4096);
#pragma unroll
        for (int u = 0; u < 4; u++) {
            u64 v2 = pack2(xv[u], xv[u]);
            const ulonglong2* wr = (const ulonglong2*)(ws + (size_t)(c + u) * 16);
#pragma unroll
            for (int q = 0; q < 8; q++) {
                ulonglong2 ww = wr[q];
                acc[2 * q + 0] = fma2(v2, ww.x, acc[2 * q + 0]);
                acc[2 * q + 1] = fma2(v2, ww.y, acc[2 * q + 1]);
            }
        }
    }

    float* dst = g_feat + (size_t)pix * 64 + hf * 32;
#pragma unroll
    for (int q = 0; q < 8; q++) {
        float f0, f1, f2, f3;
        unpack2(acc[2 * q + 0], f0, f1);
        unpack2(acc[2 * q + 1], f2, f3);
        int m0 = hf * 32 + 4 * q;
        float4 v;
        v.x = fmaxf(f0 + __ldg(bc + m0 + 0), 0.f);
        v.y = fmaxf(f1 + __ldg(bc + m0 + 1), 0.f);
        v.z = fmaxf(f2 + __ldg(bc + m0 + 2), 0.f);
        v.w = fmaxf(f3 + __ldg(bc + m0 + 3), 0.f);
        ((float4*)dst)[q] = v;
    }
}

// ============================================================
// K2: 3x3 conv + bias + softmax — SPLIT-K x4 (16 warps/block, 4096 warps)
//   grid 256 (b, row) x 512 threads; warp = (g, p), lane = px-pair
//   group g accumulates i in [16g, 16g+16); inner loop identical to R12
//   weights staged in 4 stages of 64.5KB; 3-phase smem tree reduction
// ============================================================
#define K2_FS_BYTES (64 * 200 * 4)               // 51200
#define K2_WQ_BYTES (8064 * 8)                   // 64512 = 4 groups x 2016 u64
#define K2_SMEM (K2_FS_BYTES + K2_WQ_BYTES)      // 115712

__global__ __launch_bounds__(512) void k2_conv_softmax(const float* __restrict__ benc) {
    extern __shared__ char sm2[];
    float* fs = (float*)sm2;                     // [64 i][200] (3 rows x 66 cols, pad)
    u64* wq = (u64*)(sm2 + K2_FS_BYTES);         // [4 g][4 ii][9 t][4 p][14]

    int tid = threadIdx.x;
    int bb = blockIdx.x >> 6;
    int y  = blockIdx.x & 63;
    int g    = tid >> 7;      // k-group: i in [16g, 16g+16)
    int wtid = tid & 127;
    int p  = wtid >> 5;       // warp within group = p (weight LDS broadcast)
    int xp = wtid & 31;       // lane = pixel pair: cols 2xp, 2xp+1

    // stage feat rows y-1..y+1, cols -1..64 (198 positions), all 64 i
    for (int pos = tid; pos < 198; pos += 512) {
        int r = pos / 66, cc = pos % 66;
        int iy = y + r - 1, ix = cc - 1;
        if (((unsigned)iy < 64u) && ((unsigned)ix < 64u)) {
            const float4* s4 = (const float4*)(g_feat + ((size_t)((bb * 64 + iy) * 64 + ix) << 6));
#pragma unroll
            for (int i0 = 0; i0 < 64; i0 += 4) {
                float4 v = s4[i0 >> 2];
                fs[(i0 + 0) * 200 + pos] = v.x;
                fs[(i0 + 1) * 200 + pos] = v.y;
                fs[(i0 + 2) * 200 + pos] = v.z;
                fs[(i0 + 3) * 200 + pos] = v.w;
            }
        } else {
#pragma unroll
            for (int i0 = 0; i0 < 64; i0++) fs[i0 * 200 + pos] = 0.f;
        }
    }

    u64 acc[28];              // [px(2)][14]
#pragma unroll
    for (int j = 0; j < 28; j++) acc[j] = 0ull;

    for (int s = 0; s < 4; s++) {
        __syncthreads();
        // stage: group gg gets i-range [gg*16 + s*4, +4) = 2016 u64 each
        for (int e = tid; e < 8064; e += 512) {
            int gg = e / 2016;
            int rest = e - gg * 2016;
            wq[e] = g_wp2[(size_t)(gg * 16 + s * 4) * 504 + rest];
        }
        __syncthreads();

        const u64* wg = wq + g * 2016;
#pragma unroll 1
        for (int ii = 0; ii < 4; ii++) {
            const float* fr = fs + (g * 16 + s * 4 + ii) * 200;
            float win[3][4];
#pragma unroll
            for (int dy = 0; dy < 3; dy++) {
                const float2* rp = (const float2*)(fr + dy * 66 + 2 * xp);
                float2 a = rp[0], b = rp[1];
                win[dy][0] = a.x; win[dy][1] = a.y; win[dy][2] = b.x; win[dy][3] = b.y;
            }
#pragma unroll
            for (int t = 0; t < 9; t++) {
                int dy = t / 3, dx = t % 3;
                u64 v0 = pack2(win[dy][dx], win[dy][dx]);
                u64 v1 = pack2(win[dy][dx + 1], win[dy][dx + 1]);
                const ulonglong2* wr = (const ulonglong2*)(wg + (size_t)((ii * 9 + t) * 4 + p) * 14);
#pragma unroll
                for (int q = 0; q < 7; q++) {
                    ulonglong2 ww = wr[q];
                    acc[2 * q + 0]      = fma2(v0, ww.x, acc[2 * q + 0]);
                    acc[2 * q + 1]      = fma2(v0, ww.y, acc[2 * q + 1]);
                    acc[14 + 2 * q + 0] = fma2(v1, ww.x, acc[14 + 2 * q + 0]);
                    acc[14 + 2 * q + 1] = fma2(v1, ww.y, acc[14 + 2 * q + 1]);
                }
            }
        }
    }

    // 3-phase tree reduction across the 4 groups (stride 29 -> 2-way conflicts)
    __syncthreads();
    u64* red1 = (u64*)sm2;                       // 128*29*8 = 29696B
    u64* red2 = red1 + 128 * 29;                 // second region
    if (g == 1) {
#pragma unroll
        for (int j = 0; j < 28; j++) red1[wtid * 29 + j] = acc[j];
    } else if (g == 3) {
#pragma unroll
        for (int j = 0; j < 28; j++) red2[wtid * 29 + j] = acc[j];
    }
    __syncthreads();
    if (g == 0) {
        const u64* o = red1 + wtid * 29;
#pragma unroll
        for (int j = 0; j < 28; j++) {
            float a0, a1, b0, b1;
            unpack2(acc[j], a0, a1); unpack2(o[j], b0, b1);
            acc[j] = pack2(a0 + b0, a1 + b1);
        }
    } else if (g == 2) {
        const u64* o = red2 + wtid * 29;
#pragma unroll
        for (int j = 0; j < 28; j++) {
            float a0, a1, b0, b1;
            unpack2(acc[j], a0, a1); unpack2(o[j], b0, b1);
            acc[j] = pack2(a0 + b0, a1 + b1);
        }
    }
    __syncthreads();
    if (g == 2) {
#pragma unroll
        for (int j = 0; j < 28; j++) red1[wtid * 29 + j] = acc[j];
    }
    __syncthreads();

    if (g == 0) {
        const u64* other = red1 + wtid * 29;
#pragma unroll
        for (int px = 0; px < 2; px++) {
            float l[25];
#pragma unroll
            for (int kp = 0; kp < 13; kp++) {
                float lo, hi, lo2, hi2;
                unpack2(acc[px * 14 + kp], lo, hi);
                unpack2(other[px * 14 + kp], lo2, hi2);
                l[2 * kp] = lo + lo2;
                if (2 * kp + 1 < 25) l[2 * kp + 1] = hi + hi2;
            }
            float mx = -1e30f;
#pragma unroll
            for (int k = 0; k < 25; k++) {
                l[k] += __ldg(benc + p * 25 + k);
                mx = fmaxf(mx, l[k]);
            }
            float s = 0.f;
#pragma unroll
            for (int k = 0; k < 25; k++) {
                float e = __expf(l[k] - mx);
                l[k] = e;
                s += e;
            }
            float inv = 1.f / s;
            float* dst = g_wk + (size_t)((bb * 64 + y) * 64 + 2 * xp + px) * 100 + p * 25;
#pragma unroll
            for (int k = 0; k < 25; k++) dst[k] = l[k] * inv;
        }
    }
}

// ============================================================
// K3: content-aware gather, channel-split x4 (R3 EXACT)
// ============================================================
__device__ __forceinline__ float4 fetch4(const float* __restrict__ x, int bb, int c, int h, int e) {
    int row = e / 68, col = e % 68;
    int iy = h + row - 2, ix = col - 2;
    float4 v = make_float4(0.f, 0.f, 0.f, 0.f);
    if ((unsigned)iy < 64u && (unsigned)ix < 64u) {
        const float* b = x + (((size_t)(bb * 256 + c)) << 12) + (iy << 6) + ix;
        v.x = __ldg(b);
        v.y = __ldg(b + 4096);
        v.z = __ldg(b + 8192);
        v.w = __ldg(b + 12288);
    }
    return v;
}

__global__ __launch_bounds__(256) void k3_gather(const float* __restrict__ x,
                                                 float* __restrict__ out) {
    __shared__ float wk_s[6400];
    __shared__ float4 xs[2][340];

    int tid = threadIdx.x;
    int cg = blockIdx.x & 3;
    int h  = (blockIdx.x >> 2) & 63;
    int bb = blockIdx.x >> 8;
    int w = tid >> 2;
    int p = tid & 3;
    int cbase = cg * 64;

    {
        const float4* src = (const float4*)(g_wk + (size_t)(bb * 4096 + h * 64) * 100);
        float4* dst = (float4*)wk_s;
        for (int i = tid; i < 1600; i += 256) dst[i] = src[i];
    }

    int e1 = tid;
    int e2 = tid + 256;
    bool has2 = (e2 < 340);

    float4 pf1 = fetch4(x, bb, cbase, h, e1);
    float4 pf2 = has2 ? fetch4(x, bb, cbase, h, e2) : make_float4(0, 0, 0, 0);
    xs[0][e1] = pf1;
    if (has2) xs[0][e2] = pf2;
    __syncthreads();

    u64 wk2[25];
#pragma unroll
    for (int k = 0; k < 25; k++) {
        float v = wk_s[w * 100 + p * 25 + k];
        wk2[k] = pack2(v, v);
    }

    size_t obase = ((size_t)(bb * 256 + cbase) * 4096 + (h << 6) + w) * 4 + p;

    for (int it = 0; it < 16; it++) {
        int cur = it & 1;
        if (it < 15) {
            pf1 = fetch4(x, bb, cbase + (it + 1) * 4, h, e1);
            if (has2) pf2 = fetch4(x, bb, cbase + (it + 1) * 4, h, e2);
        }

        u64 a01 = 0ull, a23 = 0ull;
        const ulonglong2* q = (const ulonglong2*)xs[cur];
#pragma unroll
        for (int k = 0; k < 25; k++) {
            int off = (k / 5) * 68 + w + (k % 5);
            ulonglong2 v = q[off];
            a01 = fma2(v.x, wk2[k], a01);
            a23 = fma2(v.y, wk2[k], a23);
        }

        if (it < 15) {
            xs[cur ^ 1][e1] = pf1;
            if (has2) xs[cur ^ 1][e2] = pf2;
        }

        float o0, o1, o2, o3;
        unpack2(a01, o0, o1);
        unpack2(a23, o2, o3);
        size_t ob = obase + (size_t)it * 4 * 16384;
        out[ob + 0 * 16384] = o0;
        out[ob + 1 * 16384] = o1;
        out[ob + 2 * 16384] = o2;
        out[ob + 3 * 16384] = o3;

        __syncthreads();
    }
}

// ============================================================
// launch: k0a, k1, k0b, k2 (4th -> profiled), k3
// ============================================================
extern "C" void kernel_launch(void* const* d_in, const int* in_sizes, int n_in,
                              void* d_out, int out_size) {
    (void)in_sizes; (void)n_in; (void)out_size;
    const float* x     = (const float*)d_in[0];
    const float* Wcomp = (const float*)d_in[1];
    const float* bcomp = (const float*)d_in[2];
    const float* Wenc  = (const float*)d_in[3];
    const float* benc  = (const float*)d_in[4];
    float* out = (float*)d_out;

    cudaFuncSetAttribute(k1_compress, cudaFuncAttributeMaxDynamicSharedMemorySize, K1_SMEM);
    cudaFuncSetAttribute(k2_conv_softmax, cudaFuncAttributeMaxDynamicSharedMemorySize, K2_SMEM);

    k0a_pack<<<32, 256>>>(Wcomp);
    k1_compress<<<256, 128, K1_SMEM>>>(x, bcomp);
    k0b_pack<<<126, 256>>>(Wenc);
    k2_conv_softmax<<<256, 512, K2_SMEM>>>(benc);
    k3_gather<<<1024, 256>>>(x, out);
}

// round 15
// speedup vs baseline: 1.0268x; 1.0268x over previous
#include <cuda_runtime.h>
#include <cstdint>

typedef unsigned long long u64;

// ---------- device scratch ----------
__device__ float g_feat[4 * 64 * 64 * 64];      // NHWC feat[pix][64]
__device__ float g_wk[4 * 64 * 64 * 100];       // softmaxed kernels
__device__ u64   g_wc2[2 * 256 * 16];           // k1 weights: [hf][c][16] pairs (m,m+1)
__device__ u64   g_wp2[64 * 9 * 4 * 14];        // k2 weights: [i][t][p][14] pairs (k,k+1), padded

// ---------- f32x2 helpers ----------
__device__ __forceinline__ u64 pack2(float lo, float hi) {
    u64 r; asm("mov.b64 %0, {%1, %2};" : "=l"(r) : "f"(lo), "f"(hi)); return r;
}
__device__ __forceinline__ void unpack2(u64 v, float& lo, float& hi) {
    asm("mov.b64 {%0, %1}, %2;" : "=f"(lo), "=f"(hi) : "l"(v));
}
__device__ __forceinline__ u64 fma2(u64 a, u64 b, u64 c) {
    u64 d; asm("fma.rn.f32x2 %0, %1, %2, %3;" : "=l"(d) : "l"(a), "l"(b), "l"(c)); return d;
}

// ============================================================
// K0: pack weights (R2 EXACT, combined)
// ============================================================
__global__ void k0_pack(const float* __restrict__ Wc, const float* __restrict__ We) {
    int e = blockIdx.x * 256 + threadIdx.x;
    if (e < 8192) {
        int j = e & 15, c = (e >> 4) & 255, hf = e >> 12;
        int m0 = hf * 32 + 2 * j;
        g_wc2[e] = pack2(Wc[(size_t)m0 * 256 + c], Wc[(size_t)(m0 + 1) * 256 + c]);
    } else if (e < 8192 + 32256) {
        int e2 = e - 8192;
        int kp = e2 % 14;
        int p  = (e2 / 14) & 3;
        int t  = (e2 / 56) % 9;
        int i  = e2 / 504;
        int o0 = p * 25 + 2 * kp;
        float lo = (2 * kp < 25)     ? We[(size_t)o0 * 576 + i * 9 + t] : 0.f;
        float hi = (2 * kp + 1 < 25) ? We[(size_t)(o0 + 1) * 576 + i * 9 + t] : 0.f;
        g_wp2[e2] = pack2(lo, hi);
    }
}

// ============================================================
// K1: feat = relu(Wc @ x + bc), NHWC output (R2 EXACT)
// ============================================================
#define K1_SMEM (4096 * 8)

__global__ __launch_bounds__(128) void k1_compress(const float* __restrict__ x,
                                                   const float* __restrict__ bc) {
    extern __shared__ u64 ws[];
    int tid = threadIdx.x;
    int hf  = blockIdx.x & 1;
    int pix = (blockIdx.x >> 1) * 128 + tid;

    const u64* src = g_wc2 + hf * 4096;
    for (int e = tid; e < 4096; e += 128) ws[e] = src[e];
    __syncthreads();

    int bb = pix >> 12, hw = pix & 4095;
    const float* xp = x + ((size_t)bb << 20) + hw;

    u64 acc[16];
#pragma unroll
    for (int j = 0; j < 16; j++) acc[j] = 0ull;

    for (int c = 0; c < 256; c += 4) {
        float xv[4];
#pragma unroll
        for (int u = 0; u < 4; u++) xv[u] = __ldg(xp + (size_t)(c + u) * 4096);
#pragma unroll
        for (int u = 0; u < 4; u++) {
            u64 v2 = pack2(xv[u], xv[u]);
            const ulonglong2* wr = (const ulonglong2*)(ws + (size_t)(c + u) * 16);
#pragma unroll
            for (int q = 0; q < 8; q++) {
                ulonglong2 ww = wr[q];
                acc[2 * q + 0] = fma2(v2, ww.x, acc[2 * q + 0]);
                acc[2 * q + 1] = fma2(v2, ww.y, acc[2 * q + 1]);
            }
        }
    }

    float* dst = g_feat + (size_t)pix * 64 + hf * 32;
#pragma unroll
    for (int q = 0; q < 8; q++) {
        float f0, f1, f2, f3;
        unpack2(acc[2 * q + 0], f0, f1);
        unpack2(acc[2 * q + 1], f2, f3);
        int m0 = hf * 32 + 4 * q;
        float4 v;
        v.x = fmaxf(f0 + __ldg(bc + m0 + 0), 0.f);
        v.y = fmaxf(f1 + __ldg(bc + m0 + 1), 0.f);
        v.z = fmaxf(f2 + __ldg(bc + m0 + 2), 0.f);
        v.w = fmaxf(f3 + __ldg(bc + m0 + 3), 0.f);
        ((float4*)dst)[q] = v;
    }
}

// ============================================================
// K2: 3x3 conv + bias + softmax — SPLIT-K x2 (R12 EXACT, best measured: 66.6us cold)
// ============================================================
#define K2_FS_BYTES (64 * 200 * 4)               // 51200
#define K2_WQ_BYTES (4032 * 8)                   // 32256 = 2 groups x 2016 u64
#define K2_SMEM (K2_FS_BYTES + K2_WQ_BYTES)

__global__ __launch_bounds__(256) void k2_conv_softmax(const float* __restrict__ benc) {
    extern __shared__ char sm2[];
    float* fs = (float*)sm2;
    u64* wq = (u64*)(sm2 + K2_FS_BYTES);

    int tid = threadIdx.x;
    int bb = blockIdx.x >> 6;
    int y  = blockIdx.x & 63;
    int g    = tid >> 7;
    int wtid = tid & 127;
    int xp = wtid & 31;
    int p  = wtid >> 5;

    for (int pos = tid; pos < 198; pos += 256) {
        int r = pos / 66, cc = pos % 66;
        int iy = y + r - 1, ix = cc - 1;
        if (((unsigned)iy < 64u) && ((unsigned)ix < 64u)) {
            const float4* s4 = (const float4*)(g_feat + ((size_t)((bb * 64 + iy) * 64 + ix) << 6));
#pragma unroll
            for (int i0 = 0; i0 < 64; i0 += 4) {
                float4 v = s4[i0 >> 2];
                fs[(i0 + 0) * 200 + pos] = v.x;
                fs[(i0 + 1) * 200 + pos] = v.y;
                fs[(i0 + 2) * 200 + pos] = v.z;
                fs[(i0 + 3) * 200 + pos] = v.w;
            }
        } else {
#pragma unroll
            for (int i0 = 0; i0 < 64; i0++) fs[i0 * 200 + pos] = 0.f;
        }
    }

    u64 acc[28];
#pragma unroll
    for (int j = 0; j < 28; j++) acc[j] = 0ull;

    for (int s = 0; s < 8; s++) {
        __syncthreads();
        for (int e = tid; e < 4032; e += 256) {
            int gg = (e >= 2016) ? 1 : 0;
            int rest = e - gg * 2016;
            wq[e] = g_wp2[(size_t)(gg * 32 + s * 4) * 504 + rest];
        }
        __syncthreads();

        const u64* wg = wq + g * 2016;
#pragma unroll 1
        for (int ii = 0; ii < 4; ii++) {
            const float* fr = fs + (g * 32 + s * 4 + ii) * 200;
            float win[3][4];
#pragma unroll
            for (int dy = 0; dy < 3; dy++) {
                const float2* rp = (const float2*)(fr + dy * 66 + 2 * xp);
                float2 a = rp[0], b = rp[1];
                win[dy][0] = a.x; win[dy][1] = a.y; win[dy][2] = b.x; win[dy][3] = b.y;
            }
#pragma unroll
            for (int t = 0; t < 9; t++) {
                int dy = t / 3, dx = t % 3;
                u64 v0 = pack2(win[dy][dx], win[dy][dx]);
                u64 v1 = pack2(win[dy][dx + 1], win[dy][dx + 1]);
                const ulonglong2* wr = (const ulonglong2*)(wg + (size_t)((ii * 9 + t) * 4 + p) * 14);
#pragma unroll
                for (int q = 0; q < 7; q++) {
                    ulonglong2 ww = wr[q];
                    acc[2 * q + 0]      = fma2(v0, ww.x, acc[2 * q + 0]);
                    acc[2 * q + 1]      = fma2(v0, ww.y, acc[2 * q + 1]);
                    acc[14 + 2 * q + 0] = fma2(v1, ww.x, acc[14 + 2 * q + 0]);
                    acc[14 + 2 * q + 1] = fma2(v1, ww.y, acc[14 + 2 * q + 1]);
                }
            }
        }
    }

    __syncthreads();
    u64* red = (u64*)sm2;
    if (g == 1) {
#pragma unroll
        for (int j = 0; j < 28; j++) red[wtid * 29 + j] = acc[j];
    }
    __syncthreads();

    if (g == 0) {
        const u64* other = red + wtid * 29;
#pragma unroll
        for (int px = 0; px < 2; px++) {
            float l[25];
#pragma unroll
            for (int kp = 0; kp < 13; kp++) {
                float lo, hi, lo2, hi2;
                unpack2(acc[px * 14 + kp], lo, hi);
                unpack2(other[px * 14 + kp], lo2, hi2);
                l[2 * kp] = lo + lo2;
                if (2 * kp + 1 < 25) l[2 * kp + 1] = hi + hi2;
            }
            float mx = -1e30f;
#pragma unroll
            for (int k = 0; k < 25; k++) {
                l[k] += __ldg(benc + p * 25 + k);
                mx = fmaxf(mx, l[k]);
            }
            float s = 0.f;
#pragma unroll
            for (int k = 0; k < 25; k++) {
                float e = __expf(l[k] - mx);
                l[k] = e;
                s += e;
            }
            float inv = 1.f / s;
            float* dst = g_wk + (size_t)((bb * 64 + y) * 64 + 2 * xp + px) * 100 + p * 25;
#pragma unroll
            for (int k = 0; k < 25; k++) dst[k] = l[k] * inv;
        }
    }
}

// ============================================================
// K3: gather — P-SHARING rewrite (halves smem traffic per FFMA2)
//   grid 1024 (b, h, cg) x 256 threads = (w 64, ph 2, cq 2)
//   thread: 2 p's x 4 channels per iter; 1 LDS.128 -> 4 FFMA2 (was 2)
//   8 iters x 8 channels; taps via contiguous LDG (no wk_s smem)
// ============================================================
__device__ __forceinline__ float4 fetch4(const float* __restrict__ x, int bb, int c, int h, int e) {
    int row = e / 68, col = e % 68;
    int iy = h + row - 2, ix = col - 2;
    float4 v = make_float4(0.f, 0.f, 0.f, 0.f);
    if ((unsigned)iy < 64u && (unsigned)ix < 64u) {
        const float* b = x + (((size_t)(bb * 256 + c)) << 12) + (iy << 6) + ix;
        v.x = __ldg(b);
        v.y = __ldg(b + 4096);
        v.z = __ldg(b + 8192);
        v.w = __ldg(b + 12288);
    }
    return v;
}

__global__ __launch_bounds__(256) void k3_gather(const float* __restrict__ x,
                                                 float* __restrict__ out) {
    __shared__ float4 xsA[2][340];        // channels c..c+3  (double-buffered)
    __shared__ float4 xsB[2][340];        // channels c+4..c+7

    int tid = threadIdx.x;
    int cg = blockIdx.x & 3;
    int h  = (blockIdx.x >> 2) & 63;
    int bb = blockIdx.x >> 8;
    int w  = tid & 63;
    int ph = (tid >> 6) & 1;              // p-half: p = 2ph, 2ph+1
    int cq = tid >> 7;                    // channel quad within 8-ch group
    int cbase = cg * 64;

    // this thread's 50 taps (p=2ph: wkf[0..25), p=2ph+1: wkf[25..50)) — contiguous
    float wkf[50];
    {
        const float2* wp = (const float2*)(g_wk + ((size_t)(bb * 4096 + h * 64 + w)) * 100 + ph * 50);
#pragma unroll
        for (int j = 0; j < 25; j++) {
            float2 v = __ldg(wp + j);
            wkf[2 * j] = v.x;
            wkf[2 * j + 1] = v.y;
        }
    }

    int e1 = tid;
    int e2 = tid + 256;
    bool has2 = (e2 < 340);

    float4 pA1 = fetch4(x, bb, cbase + 0, h, e1);
    float4 pB1 = fetch4(x, bb, cbase + 4, h, e1);
    float4 pA2 = make_float4(0, 0, 0, 0), pB2 = pA2;
    if (has2) {
        pA2 = fetch4(x, bb, cbase + 0, h, e2);
        pB2 = fetch4(x, bb, cbase + 4, h, e2);
    }
    xsA[0][e1] = pA1;
    xsB[0][e1] = pB1;
    if (has2) { xsA[0][e2] = pA2; xsB[0][e2] = pB2; }
    __syncthreads();

    // output base: ((b*256 + c)*4096 + h*64 + w)*4 + 2ph ; float2 store covers p=2ph,2ph+1
    size_t obase = ((size_t)(bb * 256) * 4096 + (h << 6) + w) * 4 + 2 * ph;

    for (int it = 0; it < 8; it++) {
        int cur = it & 1;
        if (it < 7) {
            int c0 = cbase + (it + 1) * 8;
            pA1 = fetch4(x, bb, c0 + 0, h, e1);
            pB1 = fetch4(x, bb, c0 + 4, h, e1);
            if (has2) {
                pA2 = fetch4(x, bb, c0 + 0, h, e2);
                pB2 = fetch4(x, bb, c0 + 4, h, e2);
            }
        }

        const ulonglong2* plane = (const ulonglong2*)(cq ? xsB[cur] : xsA[cur]);
        u64 a00 = 0ull, a01 = 0ull, a10 = 0ull, a11 = 0ull;
#pragma unroll
        for (int k = 0; k < 25; k++) {
            int off = (k / 5) * 68 + w + (k % 5);
            ulonglong2 v = plane[off];
            u64 w0 = pack2(wkf[k], wkf[k]);
            u64 w1 = pack2(wkf[25 + k], wkf[25 + k]);
            a00 = fma2(v.x, w0, a00);    // (c0,c1) @ p=2ph
            a01 = fma2(v.y, w0, a01);    // (c2,c3) @ p=2ph
            a10 = fma2(v.x, w1, a10);    // (c0,c1) @ p=2ph+1
            a11 = fma2(v.y, w1, a11);    // (c2,c3) @ p=2ph+1
        }

        if (it < 7) {
            xsA[cur ^ 1][e1] = pA1;
            xsB[cur ^ 1][e1] = pB1;
            if (has2) { xsA[cur ^ 1][e2] = pA2; xsB[cur ^ 1][e2] = pB2; }
        }

        float f0a, f1a, f2a, f3a, f0b, f1b, f2b, f3b;
        unpack2(a00, f0a, f1a);
        unpack2(a01, f2a, f3a);
        unpack2(a10, f0b, f1b);
        unpack2(a11, f2b, f3b);

        int c0 = it * 8 + cq * 4;       // channel offset within this cg
        size_t ob = obase + (size_t)(cbase + c0) * 16384;
        *(float2*)(out + ob + 0 * 16384) = make_float2(f0a, f0b);
        *(float2*)(out + ob + 1 * 16384) = make_float2(f1a, f1b);
        *(float2*)(out + ob + 2 * 16384) = make_float2(f2a, f2b);
        *(float2*)(out + ob + 3 * 16384) = make_float2(f3a, f3b);

        __syncthreads();
    }
}

// ============================================================
// launch: k0, k1, k2, k3 (k3 in the profiled 4th slot)
// ============================================================
extern "C" void kernel_launch(void* const* d_in, const int* in_sizes, int n_in,
                              void* d_out, int out_size) {
    (void)in_sizes; (void)n_in; (void)out_size;
    const float* x     = (const float*)d_in[0];
    const float* Wcomp = (const float*)d_in[1];
    const float* bcomp = (const float*)d_in[2];
    const float* Wenc  = (const float*)d_in[3];
    const float* benc  = (const float*)d_in[4];
    float* out = (float*)d_out;

    cudaFuncSetAttribute(k1_compress, cudaFuncAttributeMaxDynamicSharedMemorySize, K1_SMEM);
    cudaFuncSetAttribute(k2_conv_softmax, cudaFuncAttributeMaxDynamicSharedMemorySize, K2_SMEM);

    k0_pack<<<(8192 + 32256 + 255) / 256, 256>>>(Wcomp, Wenc);
    k1_compress<<<256, 128, K1_SMEM>>>(x, bcomp);
    k2_conv_softmax<<<256, 256, K2_SMEM>>>(benc);
    k3_gather<<<1024, 256>>>(x, out);
}

// round 16
// speedup vs baseline: 1.0959x; 1.0673x over previous
#include <cuda_runtime.h>
#include <cstdint>

typedef unsigned long long u64;

// ---------- device scratch ----------
__device__ float g_feat[4 * 64 * 64 * 64];      // NHWC feat[pix][64]
__device__ float g_wk[4 * 64 * 64 * 100];       // softmaxed kernels
__device__ u64   g_wc2[2 * 256 * 16];           // k1 weights: [hf][c][16] pairs (m,m+1)
__device__ u64   g_wp2[64 * 9 * 4 * 14];        // k2 weights: [i][t][p][14] pairs (k,k+1), padded

// ---------- f32x2 helpers ----------
__device__ __forceinline__ u64 pack2(float lo, float hi) {
    u64 r; asm("mov.b64 %0, {%1, %2};" : "=l"(r) : "f"(lo), "f"(hi)); return r;
}
__device__ __forceinline__ void unpack2(u64 v, float& lo, float& hi) {
    asm("mov.b64 {%0, %1}, %2;" : "=f"(lo), "=f"(hi) : "l"(v));
}
__device__ __forceinline__ u64 fma2(u64 a, u64 b, u64 c) {
    u64 d; asm("fma.rn.f32x2 %0, %1, %2, %3;" : "=l"(d) : "l"(a), "l"(b), "l"(c)); return d;
}

// ============================================================
// K0: pack weights (R2 EXACT, combined)
// ============================================================
__global__ void k0_pack(const float* __restrict__ Wc, const float* __restrict__ We) {
    int e = blockIdx.x * 256 + threadIdx.x;
    if (e < 8192) {
        int j = e & 15, c = (e >> 4) & 255, hf = e >> 12;
        int m0 = hf * 32 + 2 * j;
        g_wc2[e] = pack2(Wc[(size_t)m0 * 256 + c], Wc[(size_t)(m0 + 1) * 256 + c]);
    } else if (e < 8192 + 32256) {
        int e2 = e - 8192;
        int kp = e2 % 14;
        int p  = (e2 / 14) & 3;
        int t  = (e2 / 56) % 9;
        int i  = e2 / 504;
        int o0 = p * 25 + 2 * kp;
        float lo = (2 * kp < 25)     ? We[(size_t)o0 * 576 + i * 9 + t] : 0.f;
        float hi = (2 * kp + 1 < 25) ? We[(size_t)(o0 + 1) * 576 + i * 9 + t] : 0.f;
        g_wp2[e2] = pack2(lo, hi);
    }
}

// ============================================================
// K1: feat = relu(Wc @ x + bc), NHWC output (R2 EXACT)
// ============================================================
#define K1_SMEM (4096 * 8)

__global__ __launch_bounds__(128) void k1_compress(const float* __restrict__ x,
                                                   const float* __restrict__ bc) {
    extern __shared__ u64 ws[];
    int tid = threadIdx.x;
    int hf  = blockIdx.x & 1;
    int pix = (blockIdx.x >> 1) * 128 + tid;

    const u64* src = g_wc2 + hf * 4096;
    for (int e = tid; e < 4096; e += 128) ws[e] = src[e];
    __syncthreads();

    int bb = pix >> 12, hw = pix & 4095;
    const float* xp = x + ((size_t)bb << 20) + hw;

    u64 acc[16];
#pragma unroll
    for (int j = 0; j < 16; j++) acc[j] = 0ull;

    for (int c = 0; c < 256; c += 4) {
        float xv[4];
#pragma unroll
        for (int u = 0; u < 4; u++) xv[u] = __ldg(xp + (size_t)(c + u) * 4096);
#pragma unroll
        for (int u = 0; u < 4; u++) {
            u64 v2 = pack2(xv[u], xv[u]);
            const ulonglong2* wr = (const ulonglong2*)(ws + (size_t)(c + u) * 16);
#pragma unroll
            for (int q = 0; q < 8; q++) {
                ulonglong2 ww = wr[q];
                acc[2 * q + 0] = fma2(v2, ww.x, acc[2 * q + 0]);
                acc[2 * q + 1] = fma2(v2, ww.y, acc[2 * q + 1]);
            }
        }
    }

    float* dst = g_feat + (size_t)pix * 64 + hf * 32;
#pragma unroll
    for (int q = 0; q < 8; q++) {
        float f0, f1, f2, f3;
        unpack2(acc[2 * q + 0], f0, f1);
        unpack2(acc[2 * q + 1], f2, f3);
        int m0 = hf * 32 + 4 * q;
        float4 v;
        v.x = fmaxf(f0 + __ldg(bc + m0 + 0), 0.f);
        v.y = fmaxf(f1 + __ldg(bc + m0 + 1), 0.f);
        v.z = fmaxf(f2 + __ldg(bc + m0 + 2), 0.f);
        v.w = fmaxf(f3 + __ldg(bc + m0 + 3), 0.f);
        ((float4*)dst)[q] = v;
    }
}

// ============================================================
// K2: 3x3 conv + bias + softmax — SPLIT-K x2 (R12 EXACT, best k2: 66.6us cold)
// ============================================================
#define K2_FS_BYTES (64 * 200 * 4)               // 51200
#define K2_WQ_BYTES (4032 * 8)                   // 32256 = 2 groups x 2016 u64
#define K2_SMEM (K2_FS_BYTES + K2_WQ_BYTES)

__global__ __launch_bounds__(256) void k2_conv_softmax(const float* __restrict__ benc) {
    extern __shared__ char sm2[];
    float* fs = (float*)sm2;
    u64* wq = (u64*)(sm2 + K2_FS_BYTES);

    int tid = threadIdx.x;
    int bb = blockIdx.x >> 6;
    int y  = blockIdx.x & 63;
    int g    = tid >> 7;
    int wtid = tid & 127;
    int xp = wtid & 31;
    int p  = wtid >> 5;

    for (int pos = tid; pos < 198; pos += 256) {
        int r = pos / 66, cc = pos % 66;
        int iy = y + r - 1, ix = cc - 1;
        if (((unsigned)iy < 64u) && ((unsigned)ix < 64u)) {
            const float4* s4 = (const float4*)(g_feat + ((size_t)((bb * 64 + iy) * 64 + ix) << 6));
#pragma unroll
            for (int i0 = 0; i0 < 64; i0 += 4) {
                float4 v = s4[i0 >> 2];
                fs[(i0 + 0) * 200 + pos] = v.x;
                fs[(i0 + 1) * 200 + pos] = v.y;
                fs[(i0 + 2) * 200 + pos] = v.z;
                fs[(i0 + 3) * 200 + pos] = v.w;
            }
        } else {
#pragma unroll
            for (int i0 = 0; i0 < 64; i0++) fs[i0 * 200 + pos] = 0.f;
        }
    }

    u64 acc[28];
#pragma unroll
    for (int j = 0; j < 28; j++) acc[j] = 0ull;

    for (int s = 0; s < 8; s++) {
        __syncthreads();
        for (int e = tid; e < 4032; e += 256) {
            int gg = (e >= 2016) ? 1 : 0;
            int rest = e - gg * 2016;
            wq[e] = g_wp2[(size_t)(gg * 32 + s * 4) * 504 + rest];
        }
        __syncthreads();

        const u64* wg = wq + g * 2016;
#pragma unroll 1
        for (int ii = 0; ii < 4; ii++) {
            const float* fr = fs + (g * 32 + s * 4 + ii) * 200;
            float win[3][4];
#pragma unroll
            for (int dy = 0; dy < 3; dy++) {
                const float2* rp = (const float2*)(fr + dy * 66 + 2 * xp);
                float2 a = rp[0], b = rp[1];
                win[dy][0] = a.x; win[dy][1] = a.y; win[dy][2] = b.x; win[dy][3] = b.y;
            }
#pragma unroll
            for (int t = 0; t < 9; t++) {
                int dy = t / 3, dx = t % 3;
                u64 v0 = pack2(win[dy][dx], win[dy][dx]);
                u64 v1 = pack2(win[dy][dx + 1], win[dy][dx + 1]);
                const ulonglong2* wr = (const ulonglong2*)(wg + (size_t)((ii * 9 + t) * 4 + p) * 14);
#pragma unroll
                for (int q = 0; q < 7; q++) {
                    ulonglong2 ww = wr[q];
                    acc[2 * q + 0]      = fma2(v0, ww.x, acc[2 * q + 0]);
                    acc[2 * q + 1]      = fma2(v0, ww.y, acc[2 * q + 1]);
                    acc[14 + 2 * q + 0] = fma2(v1, ww.x, acc[14 + 2 * q + 0]);
                    acc[14 + 2 * q + 1] = fma2(v1, ww.y, acc[14 + 2 * q + 1]);
                }
            }
        }
    }

    __syncthreads();
    u64* red = (u64*)sm2;
    if (g == 1) {
#pragma unroll
        for (int j = 0; j < 28; j++) red[wtid * 29 + j] = acc[j];
    }
    __syncthreads();

    if (g == 0) {
        const u64* other = red + wtid * 29;
#pragma unroll
        for (int px = 0; px < 2; px++) {
            float l[25];
#pragma unroll
            for (int kp = 0; kp < 13; kp++) {
                float lo, hi, lo2, hi2;
                unpack2(acc[px * 14 + kp], lo, hi);
                unpack2(other[px * 14 + kp], lo2, hi2);
                l[2 * kp] = lo + lo2;
                if (2 * kp + 1 < 25) l[2 * kp + 1] = hi + hi2;
            }
            float mx = -1e30f;
#pragma unroll
            for (int k = 0; k < 25; k++) {
                l[k] += __ldg(benc + p * 25 + k);
                mx = fmaxf(mx, l[k]);
            }
            float s = 0.f;
#pragma unroll
            for (int k = 0; k < 25; k++) {
                float e = __expf(l[k] - mx);
                l[k] = e;
                s += e;
            }
            float inv = 1.f / s;
            float* dst = g_wk + (size_t)((bb * 64 + y) * 64 + 2 * xp + px) * 100 + p * 25;
#pragma unroll
            for (int k = 0; k < 25; k++) dst[k] = l[k] * inv;
        }
    }
}

// ============================================================
// K3: content-aware gather (R2 EXACT — the 144.1us champion's k3)
//   grid 256 (b,h) x 256 threads (w x p); 64 iters of 4 channels
// ============================================================
__device__ __forceinline__ float4 fetch4(const float* __restrict__ x, int bb, int c, int h, int e) {
    int row = e / 68, col = e % 68;
    int iy = h + row - 2, ix = col - 2;
    float4 v = make_float4(0.f, 0.f, 0.f, 0.f);
    if ((unsigned)iy < 64u && (unsigned)ix < 64u) {
        const float* b = x + (((size_t)(bb * 256 + c)) << 12) + (iy << 6) + ix;
        v.x = __ldg(b);
        v.y = __ldg(b + 4096);
        v.z = __ldg(b + 8192);
        v.w = __ldg(b + 12288);
    }
    return v;
}

__global__ __launch_bounds__(256) void k3_gather(const float* __restrict__ x,
                                                 float* __restrict__ out) {
    __shared__ float wk_s[6400];
    __shared__ float4 xs[2][340];

    int tid = threadIdx.x;
    int bb = blockIdx.x >> 6;
    int h = blockIdx.x & 63;
    int w = tid >> 2;
    int p = tid & 3;

    {
        const float4* src = (const float4*)(g_wk + (size_t)(bb * 4096 + h * 64) * 100);
        float4* dst = (float4*)wk_s;
        for (int i = tid; i < 1600; i += 256) dst[i] = src[i];
    }

    int e1 = tid;
    int e2 = tid + 256;
    bool has2 = (e2 < 340);

    float4 pf1 = fetch4(x, bb, 0, h, e1);
    float4 pf2 = has2 ? fetch4(x, bb, 0, h, e2) : make_float4(0, 0, 0, 0);
    xs[0][e1] = pf1;
    if (has2) xs[0][e2] = pf2;
    __syncthreads();

    u64 wk2[25];
#pragma unroll
    for (int k = 0; k < 25; k++) {
        float v = wk_s[w * 100 + p * 25 + k];
        wk2[k] = pack2(v, v);
    }

    size_t obase = ((size_t)(bb * 256) * 4096 + (h << 6) + w) * 4 + p;

    for (int it = 0; it < 64; it++) {
        int cur = it & 1;
        if (it < 63) {
            pf1 = fetch4(x, bb, (it + 1) * 4, h, e1);
            if (has2) pf2 = fetch4(x, bb, (it + 1) * 4, h, e2);
        }

        u64 a01 = 0ull, a23 = 0ull;
        const ulonglong2* q = (const ulonglong2*)xs[cur];
#pragma unroll
        for (int k = 0; k < 25; k++) {
            int off = (k / 5) * 68 + w + (k % 5);
            ulonglong2 v = q[off];
            a01 = fma2(v.x, wk2[k], a01);
            a23 = fma2(v.y, wk2[k], a23);
        }

        if (it < 63) {
            xs[cur ^ 1][e1] = pf1;
            if (has2) xs[cur ^ 1][e2] = pf2;
        }

        float o0, o1, o2, o3;
        unpack2(a01, o0, o1);
        unpack2(a23, o2, o3);
        size_t ob = obase + (size_t)it * 4 * 16384;
        out[ob + 0 * 16384] = o0;
        out[ob + 1 * 16384] = o1;
        out[ob + 2 * 16384] = o2;
        out[ob + 3 * 16384] = o3;

        __syncthreads();
    }
}

// ============================================================
// launch: k0, k1, k2, k3 (k3 in the profiled 4th slot)
// ============================================================
extern "C" void kernel_launch(void* const* d_in, const int* in_sizes, int n_in,
                              void* d_out, int out_size) {
    (void)in_sizes; (void)n_in; (void)out_size;
    const float* x     = (const float*)d_in[0];
    const float* Wcomp = (const float*)d_in[1];
    const float* bcomp = (const float*)d_in[2];
    const float* Wenc  = (const float*)d_in[3];
    const float* benc  = (const float*)d_in[4];
    float* out = (float*)d_out;

    cudaFuncSetAttribute(k1_compress, cudaFuncAttributeMaxDynamicSharedMemorySize, K1_SMEM);
    cudaFuncSetAttribute(k2_conv_softmax, cudaFuncAttributeMaxDynamicSharedMemorySize, K2_SMEM);

    k0_pack<<<(8192 + 32256 + 255) / 256, 256>>>(Wcomp, Wenc);
    k1_compress<<<256, 128, K1_SMEM>>>(x, bcomp);
    k2_conv_softmax<<<256, 256, K2_SMEM>>>(benc);
    k3_gather<<<256, 256>>>(x, out);
}

// round 17
// speedup vs baseline: 1.1327x; 1.0335x over previous
#include <cuda_runtime.h>
#include <cstdint>

typedef unsigned long long u64;

// ---------- device scratch ----------
__device__ float g_feat[4 * 64 * 64 * 64];      // NHWC feat[pix][64]
__device__ float g_wk[4 * 64 * 64 * 100];       // softmaxed kernels
__device__ u64   g_wc2[2 * 256 * 16];           // k1 weights: [hf][c][16] pairs (m,m+1)
__device__ u64   g_wp2[64 * 9 * 4 * 14];        // k2 weights: [i][t][p][14] pairs (k,k+1), padded

// ---------- f32x2 helpers ----------
__device__ __forceinline__ u64 pack2(float lo, float hi) {
    u64 r; asm("mov.b64 %0, {%1, %2};" : "=l"(r) : "f"(lo), "f"(hi)); return r;
}
__device__ __forceinline__ void unpack2(u64 v, float& lo, float& hi) {
    asm("mov.b64 {%0, %1}, %2;" : "=f"(lo), "=f"(hi) : "l"(v));
}
__device__ __forceinline__ u64 fma2(u64 a, u64 b, u64 c) {
    u64 d; asm("fma.rn.f32x2 %0, %1, %2, %3;" : "=l"(d) : "l"(a), "l"(b), "l"(c)); return d;
}

// ============================================================
// K0: pack weights (R2 EXACT, combined)
// ============================================================
__global__ void k0_pack(const float* __restrict__ Wc, const float* __restrict__ We) {
    int e = blockIdx.x * 256 + threadIdx.x;
    if (e < 8192) {
        int j = e & 15, c = (e >> 4) & 255, hf = e >> 12;
        int m0 = hf * 32 + 2 * j;
        g_wc2[e] = pack2(Wc[(size_t)m0 * 256 + c], Wc[(size_t)(m0 + 1) * 256 + c]);
    } else if (e < 8192 + 32256) {
        int e2 = e - 8192;
        int kp = e2 % 14;
        int p  = (e2 / 14) & 3;
        int t  = (e2 / 56) % 9;
        int i  = e2 / 504;
        int o0 = p * 25 + 2 * kp;
        float lo = (2 * kp < 25)     ? We[(size_t)o0 * 576 + i * 9 + t] : 0.f;
        float hi = (2 * kp + 1 < 25) ? We[(size_t)(o0 + 1) * 576 + i * 9 + t] : 0.f;
        g_wp2[e2] = pack2(lo, hi);
    }
}

// ============================================================
// K1: feat = relu(Wc @ x + bc), NHWC output — SPLIT-K x2 (validated transform)
//   grid 256 (128 px-groups x 2 m-halves) x 256 threads
//   group g accumulates c in [128g, 128g+128); inner loop byte-identical to R2
//   reduction reuses weight smem region after barrier (stride 17)
// ============================================================
#define K1_SMEM (4096 * 8)

__global__ __launch_bounds__(256) void k1_compress(const float* __restrict__ x,
                                                   const float* __restrict__ bc) {
    extern __shared__ u64 ws[];      // [256][16] packed pairs for this half
    int tid = threadIdx.x;
    int hf  = blockIdx.x & 1;
    int g    = tid >> 7;             // k-group: c in [128g, 128g+128)
    int wtid = tid & 127;
    int pix = (blockIdx.x >> 1) * 128 + wtid;

    const u64* src = g_wc2 + hf * 4096;
    for (int e = tid; e < 4096; e += 256) ws[e] = src[e];
    __syncthreads();

    int bb = pix >> 12, hw = pix & 4095;
    const float* xp = x + ((size_t)bb << 20) + hw + ((size_t)g << 19);  // + g*128*4096

    u64 acc[16];
#pragma unroll
    for (int j = 0; j < 16; j++) acc[j] = 0ull;

    int cbase = g * 128;
    for (int c = 0; c < 128; c += 4) {
        float xv[4];
#pragma unroll
        for (int u = 0; u < 4; u++) xv[u] = __ldg(xp + (size_t)(c + u) * 4096);
#pragma unroll
        for (int u = 0; u < 4; u++) {
            u64 v2 = pack2(xv[u], xv[u]);
            const ulonglong2* wr = (const ulonglong2*)(ws + (size_t)(cbase + c + u) * 16);
#pragma unroll
            for (int q = 0; q < 8; q++) {
                ulonglong2 ww = wr[q];
                acc[2 * q + 0] = fma2(v2, ww.x, acc[2 * q + 0]);
                acc[2 * q + 1] = fma2(v2, ww.y, acc[2 * q + 1]);
            }
        }
    }

    // reduce across the 2 groups (reuse ws after all reads complete)
    __syncthreads();
    u64* red = ws;                   // 128 * 17 * 8 = 17408 B < 32 KB
    if (g == 1) {
#pragma unroll
        for (int j = 0; j < 16; j++) red[wtid * 17 + j] = acc[j];
    }
    __syncthreads();

    if (g == 0) {
        const u64* other = red + wtid * 17;
        float* dst = g_feat + (size_t)pix * 64 + hf * 32;
#pragma unroll
        for (int q = 0; q < 8; q++) {
            float f0, f1, f2, f3, g0, g1, g2, g3;
            unpack2(acc[2 * q + 0], f0, f1);
            unpack2(acc[2 * q + 1], f2, f3);
            unpack2(other[2 * q + 0], g0, g1);
            unpack2(other[2 * q + 1], g2, g3);
            int m0 = hf * 32 + 4 * q;
            float4 v;
            v.x = fmaxf(f0 + g0 + __ldg(bc + m0 + 0), 0.f);
            v.y = fmaxf(f1 + g1 + __ldg(bc + m0 + 1), 0.f);
            v.z = fmaxf(f2 + g2 + __ldg(bc + m0 + 2), 0.f);
            v.w = fmaxf(f3 + g3 + __ldg(bc + m0 + 3), 0.f);
            ((float4*)dst)[q] = v;
        }
    }
}

// ============================================================
// K2: 3x3 conv + bias + softmax — SPLIT-K x2 (R12 EXACT, best k2: 66.6us cold)
// ============================================================
#define K2_FS_BYTES (64 * 200 * 4)               // 51200
#define K2_WQ_BYTES (4032 * 8)                   // 32256 = 2 groups x 2016 u64
#define K2_SMEM (K2_FS_BYTES + K2_WQ_BYTES)

__global__ __launch_bounds__(256) void k2_conv_softmax(const float* __restrict__ benc) {
    extern __shared__ char sm2[];
    float* fs = (float*)sm2;
    u64* wq = (u64*)(sm2 + K2_FS_BYTES);

    int tid = threadIdx.x;
    int bb = blockIdx.x >> 6;
    int y  = blockIdx.x & 63;
    int g    = tid >> 7;
    int wtid = tid & 127;
    int xp = wtid & 31;
    int p  = wtid >> 5;

    for (int pos = tid; pos < 198; pos += 256) {
        int r = pos / 66, cc = pos % 66;
        int iy = y + r - 1, ix = cc - 1;
        if (((unsigned)iy < 64u) && ((unsigned)ix < 64u)) {
            const float4* s4 = (const float4*)(g_feat + ((size_t)((bb * 64 + iy) * 64 + ix) << 6));
#pragma unroll
            for (int i0 = 0; i0 < 64; i0 += 4) {
                float4 v = s4[i0 >> 2];
                fs[(i0 + 0) * 200 + pos] = v.x;
                fs[(i0 + 1) * 200 + pos] = v.y;
                fs[(i0 + 2) * 200 + pos] = v.z;
                fs[(i0 + 3) * 200 + pos] = v.w;
            }
        } else {
#pragma unroll
            for (int i0 = 0; i0 < 64; i0++) fs[i0 * 200 + pos] = 0.f;
        }
    }

    u64 acc[28];
#pragma unroll
    for (int j = 0; j < 28; j++) acc[j] = 0ull;

    for (int s = 0; s < 8; s++) {
        __syncthreads();
        for (int e = tid; e < 4032; e += 256) {
            int gg = (e >= 2016) ? 1 : 0;
            int rest = e - gg * 2016;
            wq[e] = g_wp2[(size_t)(gg * 32 + s * 4) * 504 + rest];
        }
        __syncthreads();

        const u64* wg = wq + g * 2016;
#pragma unroll 1
        for (int ii = 0; ii < 4; ii++) {
            const float* fr = fs + (g * 32 + s * 4 + ii) * 200;
            float win[3][4];
#pragma unroll
            for (int dy = 0; dy < 3; dy++) {
                const float2* rp = (const float2*)(fr + dy * 66 + 2 * xp);
                float2 a = rp[0], b = rp[1];
                win[dy][0] = a.x; win[dy][1] = a.y; win[dy][2] = b.x; win[dy][3] = b.y;
            }
#pragma unroll
            for (int t = 0; t < 9; t++) {
                int dy = t / 3, dx = t % 3;
                u64 v0 = pack2(win[dy][dx], win[dy][dx]);
                u64 v1 = pack2(win[dy][dx + 1], win[dy][dx + 1]);
                const ulonglong2* wr = (const ulonglong2*)(wg + (size_t)((ii * 9 + t) * 4 + p) * 14);
#pragma unroll
                for (int q = 0; q < 7; q++) {
                    ulonglong2 ww = wr[q];
                    acc[2 * q + 0]      = fma2(v0, ww.x, acc[2 * q + 0]);
                    acc[2 * q + 1]      = fma2(v0, ww.y, acc[2 * q + 1]);
                    acc[14 + 2 * q + 0] = fma2(v1, ww.x, acc[14 + 2 * q + 0]);
                    acc[14 + 2 * q + 1] = fma2(v1, ww.y, acc[14 + 2 * q + 1]);
                }
            }
        }
    }

    __syncthreads();
    u64* red = (u64*)sm2;
    if (g == 1) {
#pragma unroll
        for (int j = 0; j < 28; j++) red[wtid * 29 + j] = acc[j];
    }
    __syncthreads();

    if (g == 0) {
        const u64* other = red + wtid * 29;
#pragma unroll
        for (int px = 0; px < 2; px++) {
            float l[25];
#pragma unroll
            for (int kp = 0; kp < 13; kp++) {
                float lo, hi, lo2, hi2;
                unpack2(acc[px * 14 + kp], lo, hi);
                unpack2(other[px * 14 + kp], lo2, hi2);
                l[2 * kp] = lo + lo2;
                if (2 * kp + 1 < 25) l[2 * kp + 1] = hi + hi2;
            }
            float mx = -1e30f;
#pragma unroll
            for (int k = 0; k < 25; k++) {
                l[k] += __ldg(benc + p * 25 + k);
                mx = fmaxf(mx, l[k]);
            }
            float s = 0.f;
#pragma unroll
            for (int k = 0; k < 25; k++) {
                float e = __expf(l[k] - mx);
                l[k] = e;
                s += e;
            }
            float inv = 1.f / s;
            float* dst = g_wk + (size_t)((bb * 64 + y) * 64 + 2 * xp + px) * 100 + p * 25;
#pragma unroll
            for (int k = 0; k < 25; k++) dst[k] = l[k] * inv;
        }
    }
}

// ============================================================
// K3: content-aware gather (R2 EXACT — champion's k3)
// ============================================================
__device__ __forceinline__ float4 fetch4(const float* __restrict__ x, int bb, int c, int h, int e) {
    int row = e / 68, col = e % 68;
    int iy = h + row - 2, ix = col - 2;
    float4 v = make_float4(0.f, 0.f, 0.f, 0.f);
    if ((unsigned)iy < 64u && (unsigned)ix < 64u) {
        const float* b = x + (((size_t)(bb * 256 + c)) << 12) + (iy << 6) + ix;
        v.x = __ldg(b);
        v.y = __ldg(b + 4096);
        v.z = __ldg(b + 8192);
        v.w = __ldg(b + 12288);
    }
    return v;
}

__global__ __launch_bounds__(256) void k3_gather(const float* __restrict__ x,
                                                 float* __restrict__ out) {
    __shared__ float wk_s[6400];
    __shared__ float4 xs[2][340];

    int tid = threadIdx.x;
    int bb = blockIdx.x >> 6;
    int h = blockIdx.x & 63;
    int w = tid >> 2;
    int p = tid & 3;

    {
        const float4* src = (const float4*)(g_wk + (size_t)(bb * 4096 + h * 64) * 100);
        float4* dst = (float4*)wk_s;
        for (int i = tid; i < 1600; i += 256) dst[i] = src[i];
    }

    int e1 = tid;
    int e2 = tid + 256;
    bool has2 = (e2 < 340);

    float4 pf1 = fetch4(x, bb, 0, h, e1);
    float4 pf2 = has2 ? fetch4(x, bb, 0, h, e2) : make_float4(0, 0, 0, 0);
    xs[0][e1] = pf1;
    if (has2) xs[0][e2] = pf2;
    __syncthreads();

    u64 wk2[25];
#pragma unroll
    for (int k = 0; k < 25; k++) {
        float v = wk_s[w * 100 + p * 25 + k];
        wk2[k] = pack2(v, v);
    }

    size_t obase = ((size_t)(bb * 256) * 4096 + (h << 6) + w) * 4 + p;

    for (int it = 0; it < 64; it++) {
        int cur = it & 1;
        if (it < 63) {
            pf1 = fetch4(x, bb, (it + 1) * 4, h, e1);
            if (has2) pf2 = fetch4(x, bb, (it + 1) * 4, h, e2);
        }

        u64 a01 = 0ull, a23 = 0ull;
        const ulonglong2* q = (const ulonglong2*)xs[cur];
#pragma unroll
        for (int k = 0; k < 25; k++) {
            int off = (k / 5) * 68 + w + (k % 5);
            ulonglong2 v = q[off];
            a01 = fma2(v.x, wk2[k], a01);
            a23 = fma2(v.y, wk2[k], a23);
        }

        if (it < 63) {
            xs[cur ^ 1][e1] = pf1;
            if (has2) xs[cur ^ 1][e2] = pf2;
        }

        float o0, o1, o2, o3;
        unpack2(a01, o0, o1);
        unpack2(a23, o2, o3);
        size_t ob = obase + (size_t)it * 4 * 16384;
        out[ob + 0 * 16384] = o0;
        out[ob + 1 * 16384] = o1;
        out[ob + 2 * 16384] = o2;
        out[ob + 3 * 16384] = o3;

        __syncthreads();
    }
}

// ============================================================
// launch: k0, k1, k2, k3 (k3 in the profiled 4th slot)
// ============================================================
extern "C" void kernel_launch(void* const* d_in, const int* in_sizes, int n_in,
                              void* d_out, int out_size) {
    (void)in_sizes; (void)n_in; (void)out_size;
    const float* x     = (const float*)d_in[0];
    const float* Wcomp = (const float*)d_in[1];
    const float* bcomp = (const float*)d_in[2];
    const float* Wenc  = (const float*)d_in[3];
    const float* benc  = (const float*)d_in[4];
    float* out = (float*)d_out;

    cudaFuncSetAttribute(k1_compress, cudaFuncAttributeMaxDynamicSharedMemorySize, K1_SMEM);
    cudaFuncSetAttribute(k2_conv_softmax, cudaFuncAttributeMaxDynamicSharedMemorySize, K2_SMEM);

    k0_pack<<<(8192 + 32256 + 255) / 256, 256>>>(Wcomp, Wenc);
    k1_compress<<<256, 256, K1_SMEM>>>(x, bcomp);
    k2_conv_softmax<<<256, 256, K2_SMEM>>>(benc);
    k3_gather<<<256, 256>>>(x, out);
}